// round 5
// baseline (speedup 1.0000x reference)
// BitNet-style FFN on GB300 — sm_103 BASELINE ISA build (harness ptxas target is
// plain sm_103: tcgen05/TMEM/TMA are rejected, confirmed Round 2). So: Ampere-style
// pipeline — cp.async + ldmatrix + mma.sync.m16n8k16 f16f16f32.
//   out = gelu_exact(x @ T(W1)^T + b1) @ T(W2)^T + b2,  T() = absmean ternary {-1,0,1}
// Ternary weights EXACT in fp16; x/H fp16, fp32 accumulators -> rel_err ~5e-4.

#include <cuda_runtime.h>
#include <cuda_fp16.h>
#include <cstdint>

#define EMB 1024
#define FF 4096
#define NTOK 8192
#define WN (FF * EMB)

// ---------------- device-global scratch (allocation-free rule) ----------------
__device__ __align__(16) __half g_Xh[(size_t)NTOK * EMB];   // 16 MB
__device__ __align__(16) __half g_W1t[(size_t)FF * EMB];    // 8 MB
__device__ __align__(16) __half g_W2t[(size_t)FF * EMB];    // 8 MB
__device__ __align__(16) __half g_H[(size_t)NTOK * FF];     // 64 MB
__device__ float g_partial[2048];
__device__ float g_scale[2];

// ---------------- PTX helpers (baseline ISA only) ----------------
__device__ __forceinline__ uint32_t smem_u32(const void* p) {
    uint32_t a;
    asm("{ .reg .u64 t; cvta.to.shared.u64 t, %1; cvt.u32.u64 %0, t; }" : "=r"(a) : "l"(p));
    return a;
}

#define CP16(dst, src) \
    asm volatile("cp.async.cg.shared.global [%0], [%1], 16;" \
                 :: "r"((uint32_t)(dst)), "l"(__cvta_generic_to_global(src)) : "memory")
#define CP_COMMIT()  asm volatile("cp.async.commit_group;" ::: "memory")
#define CP_WAIT2()   asm volatile("cp.async.wait_group 2;" ::: "memory")

#define LDSM4(r0, r1, r2, r3, addr) \
    asm volatile("ldmatrix.sync.aligned.m8n8.x4.shared.b16 {%0,%1,%2,%3}, [%4];" \
                 : "=r"(r0), "=r"(r1), "=r"(r2), "=r"(r3) : "r"(addr))

#define MMA16816(d, a0, a1, a2, a3, b0, b1) \
    asm volatile("mma.sync.aligned.m16n8k16.row.col.f32.f16.f16.f32 " \
                 "{%0,%1,%2,%3}, {%4,%5,%6,%7}, {%8,%9}, {%0,%1,%2,%3};" \
                 : "+f"((d)[0]), "+f"((d)[1]), "+f"((d)[2]), "+f"((d)[3]) \
                 : "r"(a0), "r"(a1), "r"(a2), "r"(a3), "r"(b0), "r"(b1))

// ---------------- GEMM configuration ----------------
constexpr int BM = 128, BN = 128, BK = 64, NST = 4, TPB = 256;
constexpr int A_BYTES = BM * 128;            // 16 KB (128 rows x 64 halves = 128 B/row)
constexpr int B_BYTES = BN * 128;            // 16 KB
constexpr int STG_BYTES = A_BYTES + B_BYTES; // 32 KB
constexpr int SM_BIAS = 0, SM_TILES = 1024;
constexpr int SMEM_TOTAL = SM_TILES + NST * STG_BYTES;   // 132 KB

// Per-stage tile loader. A and B are both K-major, 64 halves (=8x16B segs) per row.
// SW128 swizzle: seg' = seg ^ (row & 7)  -> conflict-free ldmatrix + cp.async.
__device__ __forceinline__ void load_tile(uint32_t sb, int stage,
                                          const __half* __restrict__ A,
                                          const __half* __restrict__ B,
                                          int m0, int n0, int kc, int K, int tid) {
    uint32_t sa = sb + SM_TILES + stage * STG_BYTES;
    uint32_t sB = sa + A_BYTES;
    #pragma unroll
    for (int t = 0; t < 4; t++) {
        int i = tid + t * TPB;              // 0..1023
        int r = i >> 3, s = i & 7;
        uint32_t dst = sa + r * 128 + ((s ^ (r & 7)) << 4);
        CP16(dst, A + (size_t)(m0 + r) * K + kc + s * 8);
    }
    #pragma unroll
    for (int t = 0; t < 4; t++) {
        int i = tid + t * TPB;
        int r = i >> 3, s = i & 7;
        uint32_t dst = sB + r * 128 + ((s ^ (r & 7)) << 4);
        CP16(dst, B + (size_t)(n0 + r) * K + kc + s * 8);
    }
}

// ---------------- fused GEMM + epilogue ----------------
// GELU=true : A=g_Xh [8192,1024], B=g_W1t [4096,1024], out=g_H (fp16), +b1, erf-GELU
// GELU=false: A=g_H  [8192,4096], B=g_W2t [1024,4096], out=out_f (fp32), +b2
template <bool GELU>
__global__ void __launch_bounds__(TPB, 1)
ffn_gemm(const float* __restrict__ bias, float* __restrict__ out_f) {
    extern __shared__ __align__(1024) uint8_t smem_raw[];
    uint32_t sb = smem_u32(smem_raw);
    const int tid = threadIdx.x;
    const int lane = tid & 31, warp = tid >> 5;
    const int wm = warp & 1;        // 0..1 -> 64-row slice
    const int wn = warp >> 1;       // 0..3 -> 32-col slice
    const int m0 = blockIdx.y * BM;
    const int n0 = blockIdx.x * BN;
    constexpr int K = GELU ? EMB : FF;
    constexpr int Npar = GELU ? FF : EMB;
    constexpr int NC = K / BK;

    const __half* A = GELU ? g_Xh : g_H;
    const __half* B = GELU ? g_W1t : g_W2t;

    float* bias_s = reinterpret_cast<float*>(smem_raw + SM_BIAS);
    for (int i = tid; i < BN; i += TPB) bias_s[i] = bias[n0 + i];

    // ldmatrix lane -> (row offset, k-half) precompute
    const int a_roff = (lane & 7) + ((lane >> 3) & 1) * 8;  // matrices: mLo/kLo, mHi/kLo, mLo/kHi, mHi/kHi
    const int a_hi   = (lane >> 4) & 1;
    const int b_noff = (lane & 7) + ((lane >> 4) & 1) * 8;  // matrices: nLo/kLo, nLo/kHi, nHi/kLo, nHi/kHi
    const int b_hi   = (lane >> 3) & 1;

    float acc[4][4][4];
    #pragma unroll
    for (int mt = 0; mt < 4; mt++)
        #pragma unroll
        for (int nt = 0; nt < 4; nt++)
            #pragma unroll
            for (int e = 0; e < 4; e++) acc[mt][nt][e] = 0.f;

    // prologue: 3 stages in flight
    load_tile(sb, 0, A, B, m0, n0, 0, K, tid);      CP_COMMIT();
    load_tile(sb, 1, A, B, m0, n0, BK, K, tid);     CP_COMMIT();
    load_tile(sb, 2, A, B, m0, n0, 2 * BK, K, tid); CP_COMMIT();

    // per-lane A row addrs (byte offset within stage) for the 4 m-tiles
    uint32_t a_rowb[4]; int a_rc[4];
    #pragma unroll
    for (int mt = 0; mt < 4; mt++) {
        int r = wm * 64 + mt * 16 + a_roff;
        a_rowb[mt] = r * 128;
        a_rc[mt] = r & 7;
    }
    uint32_t b_rowb[2]; int b_rc[2];
    #pragma unroll
    for (int p = 0; p < 2; p++) {
        int r = wn * 32 + p * 16 + b_noff;
        b_rowb[p] = r * 128;
        b_rc[p] = r & 7;
    }

    for (int i = 0; i < NC; i++) {
        CP_WAIT2();           // oldest in-flight group (chunk i) complete
        __syncthreads();      // all warps done with stage (i-1)&3 from last iter
        int pf = i + 3;
        if (pf < NC) load_tile(sb, pf & 3, A, B, m0, n0, pf * BK, K, tid);
        CP_COMMIT();

        uint32_t sa = sb + SM_TILES + (i & 3) * STG_BYTES;
        uint32_t sB = sa + A_BYTES;
        #pragma unroll
        for (int kk = 0; kk < 4; kk++) {   // 4 x k16 steps per BK=64 chunk
            uint32_t ar[4][4], br[2][4];
            #pragma unroll
            for (int mt = 0; mt < 4; mt++) {
                int s = 2 * kk + a_hi;
                uint32_t ad = sa + a_rowb[mt] + ((s ^ a_rc[mt]) << 4);
                LDSM4(ar[mt][0], ar[mt][1], ar[mt][2], ar[mt][3], ad);
            }
            #pragma unroll
            for (int p = 0; p < 2; p++) {
                int s = 2 * kk + b_hi;
                uint32_t bd = sB + b_rowb[p] + ((s ^ b_rc[p]) << 4);
                LDSM4(br[p][0], br[p][1], br[p][2], br[p][3], bd);
            }
            #pragma unroll
            for (int mt = 0; mt < 4; mt++)
                #pragma unroll
                for (int nt = 0; nt < 4; nt++) {
                    int p = nt >> 1, h = (nt & 1) << 1;
                    MMA16816(acc[mt][nt], ar[mt][0], ar[mt][1], ar[mt][2], ar[mt][3],
                             br[p][h], br[p][h + 1]);
                }
        }
    }

    // ---------------- epilogue: fragments -> bias (+GELU) -> global ----------------
    const int mrow = lane >> 2;            // 0..7
    const int ncol = (lane & 3) * 2;       // 0,2,4,6
    #pragma unroll
    for (int mt = 0; mt < 4; mt++) {
        #pragma unroll
        for (int nt = 0; nt < 4; nt++) {
            int col_l = wn * 32 + nt * 8 + ncol;
            float bi0 = bias_s[col_l], bi1 = bias_s[col_l + 1];
            #pragma unroll
            for (int half = 0; half < 2; half++) {   // d0d1 (m+0) / d2d3 (m+8)
                int row = m0 + wm * 64 + mt * 16 + mrow + half * 8;
                float v0 = acc[mt][nt][2 * half]     + bi0;
                float v1 = acc[mt][nt][2 * half + 1] + bi1;
                if (GELU) {
                    v0 = 0.5f * v0 * (1.0f + erff(v0 * 0.70710678118654752f));
                    v1 = 0.5f * v1 * (1.0f + erff(v1 * 0.70710678118654752f));
                }
                size_t off = (size_t)row * Npar + n0 + col_l;
                if (GELU) {
                    __half2 h2 = __floats2half2_rn(v0, v1);
                    *reinterpret_cast<__half2*>(g_H + off) = h2;
                } else {
                    float2 f2; f2.x = v0; f2.y = v1;
                    *reinterpret_cast<float2*>(out_f + off) = f2;
                }
            }
        }
    }
}

// ---------------- preprocessing ----------------
__global__ void absmean_partial_k(const float4* __restrict__ w, int poff) {
    __shared__ float sm[256];
    float s = 0.f;
    const int total = WN / 4;
    for (int i = blockIdx.x * 256 + threadIdx.x; i < total; i += 1024 * 256) {
        float4 v = w[i];
        s += fabsf(v.x) + fabsf(v.y) + fabsf(v.z) + fabsf(v.w);
    }
    sm[threadIdx.x] = s;
    __syncthreads();
    #pragma unroll
    for (int d = 128; d > 0; d >>= 1) {
        if (threadIdx.x < d) sm[threadIdx.x] += sm[threadIdx.x + d];
        __syncthreads();
    }
    if (threadIdx.x == 0) g_partial[poff + blockIdx.x] = sm[0];
}

__global__ void absmean_final_k() {
    __shared__ float sm[1024];
    sm[threadIdx.x] = g_partial[blockIdx.x * 1024 + threadIdx.x];
    __syncthreads();
    #pragma unroll
    for (int d = 512; d > 0; d >>= 1) {
        if (threadIdx.x < d) sm[threadIdx.x] += sm[threadIdx.x + d];
        __syncthreads();
    }
    if (threadIdx.x == 0) g_scale[blockIdx.x] = fmaxf(sm[0] / (float)WN, 1e-8f);
}

__global__ void quant_k(const float4* __restrict__ w, int which) {
    __half* o = which ? g_W2t : g_W1t;
    float inv = 1.0f / g_scale[which];
    int i = blockIdx.x * 256 + threadIdx.x;   // grid covers WN/4 exactly
    float4 v = w[i];
    float a = fminf(fmaxf(rintf(v.x * inv), -1.f), 1.f);
    float b = fminf(fmaxf(rintf(v.y * inv), -1.f), 1.f);
    float c = fminf(fmaxf(rintf(v.z * inv), -1.f), 1.f);
    float d = fminf(fmaxf(rintf(v.w * inv), -1.f), 1.f);
    __half2 h0 = __floats2half2_rn(a, b);
    __half2 h1 = __floats2half2_rn(c, d);
    uint2 u;
    u.x = *reinterpret_cast<uint32_t*>(&h0);
    u.y = *reinterpret_cast<uint32_t*>(&h1);
    *reinterpret_cast<uint2*>(o + (size_t)i * 4) = u;
}

__global__ void x2h_k(const float4* __restrict__ x) {
    int i = blockIdx.x * 256 + threadIdx.x;   // grid covers NTOK*EMB/4 exactly
    float4 v = x[i];
    __half2 h0 = __floats2half2_rn(v.x, v.y);
    __half2 h1 = __floats2half2_rn(v.z, v.w);
    uint2 u;
    u.x = *reinterpret_cast<uint32_t*>(&h0);
    u.y = *reinterpret_cast<uint32_t*>(&h1);
    *reinterpret_cast<uint2*>(g_Xh + (size_t)i * 4) = u;
}

// ---------------- launcher ----------------
extern "C" void kernel_launch(void* const* d_in, const int* in_sizes, int n_in,
                              void* d_out, int out_size) {
    const float* x  = (const float*)d_in[0];
    const float* W1 = (const float*)d_in[1];
    const float* b1 = (const float*)d_in[2];
    const float* W2 = (const float*)d_in[3];
    const float* b2 = (const float*)d_in[4];
    float* out = (float*)d_out;

    cudaFuncSetAttribute(ffn_gemm<true>,  cudaFuncAttributeMaxDynamicSharedMemorySize, SMEM_TOTAL);
    cudaFuncSetAttribute(ffn_gemm<false>, cudaFuncAttributeMaxDynamicSharedMemorySize, SMEM_TOTAL);

    absmean_partial_k<<<1024, 256>>>((const float4*)W1, 0);
    absmean_partial_k<<<1024, 256>>>((const float4*)W2, 1024);
    absmean_final_k<<<2, 1024>>>();
    quant_k<<<WN / 4 / 256, 256>>>((const float4*)W1, 0);
    quant_k<<<WN / 4 / 256, 256>>>((const float4*)W2, 1);
    x2h_k<<<NTOK * EMB / 4 / 256, 256>>>((const float4*)x);

    ffn_gemm<true><<<dim3(FF / BN, NTOK / BM), TPB, SMEM_TOTAL>>>(b1, nullptr);
    ffn_gemm<false><<<dim3(EMB / BN, NTOK / BM), TPB, SMEM_TOTAL>>>(b2, out);
}

// round 7
// speedup vs baseline: 1.1207x; 1.1207x over previous
// BitNet-style FFN on GB300 — sm_103 baseline-ISA build (tcgen05 rejected by the
// harness's ptxas target; confirmed Round 2). Ampere-style pipeline:
// cp.async + ldmatrix + mma.sync.m16n8k16.f32.f16.f16.f32.
//   out = gelu_exact(x @ T(W1)^T + b1) @ T(W2)^T + b2,  T() = absmean ternary {-1,0,1}
// Ternary weights EXACT in fp16; x/H fp16, fp32 accumulators -> rel_err ~3e-4.
// R6: 64x64 warp tiles (BM=128,BN=256) -> smem crossbar no longer the binding pipe
//     (128 B/MMA = exactly the 128 B/cyc break-even vs 192 B/MMA before).

#include <cuda_runtime.h>
#include <cuda_fp16.h>
#include <cstdint>

#define EMB 1024
#define FF 4096
#define NTOK 8192
#define WN (FF * EMB)
#define XN (NTOK * EMB)

// ---------------- device-global scratch (allocation-free rule) ----------------
__device__ __align__(16) __half g_Xh[(size_t)NTOK * EMB];   // 16 MB
__device__ __align__(16) __half g_W1t[(size_t)FF * EMB];    // 8 MB
__device__ __align__(16) __half g_W2t[(size_t)FF * EMB];    // 8 MB
__device__ __align__(16) __half g_H[(size_t)NTOK * FF];     // 64 MB
__device__ float g_partial[2048];
__device__ float g_scale[2];

// ---------------- PTX helpers (baseline ISA only) ----------------
__device__ __forceinline__ uint32_t smem_u32(const void* p) {
    uint32_t a;
    asm("{ .reg .u64 t; cvta.to.shared.u64 t, %1; cvt.u32.u64 %0, t; }" : "=r"(a) : "l"(p));
    return a;
}

#define CP16(dst, src) \
    asm volatile("cp.async.cg.shared.global [%0], [%1], 16;" \
                 :: "r"((uint32_t)(dst)), "l"(__cvta_generic_to_global(src)) : "memory")
#define CP_COMMIT()  asm volatile("cp.async.commit_group;" ::: "memory")
#define CP_WAIT2()   asm volatile("cp.async.wait_group 2;" ::: "memory")

#define LDSM4(r0, r1, r2, r3, addr) \
    asm volatile("ldmatrix.sync.aligned.m8n8.x4.shared.b16 {%0,%1,%2,%3}, [%4];" \
                 : "=r"(r0), "=r"(r1), "=r"(r2), "=r"(r3) : "r"(addr))

#define MMA16816(d, a0, a1, a2, a3, b0, b1) \
    asm volatile("mma.sync.aligned.m16n8k16.row.col.f32.f16.f16.f32 " \
                 "{%0,%1,%2,%3}, {%4,%5,%6,%7}, {%8,%9}, {%0,%1,%2,%3};" \
                 : "+f"((d)[0]), "+f"((d)[1]), "+f"((d)[2]), "+f"((d)[3]) \
                 : "r"(a0), "r"(a1), "r"(a2), "r"(a3), "r"(b0), "r"(b1))

// ---------------- GEMM configuration ----------------
constexpr int BM = 128, BN = 256, BK = 64, NST = 4, TPB = 256;
constexpr int A_BYTES = BM * 128;            // 16 KB (128 rows x 64 halves = 128 B/row)
constexpr int B_BYTES = BN * 128;            // 32 KB
constexpr int STG_BYTES = A_BYTES + B_BYTES; // 48 KB
constexpr int SM_BIAS = 0, SM_TILES = 2048;
constexpr int SMEM_TOTAL = SM_TILES + NST * STG_BYTES;   // 198656 B

// Per-stage tile loader. A and B both K-major, 64 halves (= 8 x 16B segs) per row.
// SW128 swizzle: seg' = seg ^ (row & 7) -> conflict-free cp.async + ldmatrix.
__device__ __forceinline__ void load_tile(uint32_t sb, int stage,
                                          const __half* __restrict__ A,
                                          const __half* __restrict__ B,
                                          int m0, int n0, int kc, int K, int tid) {
    uint32_t sa = sb + SM_TILES + stage * STG_BYTES;
    uint32_t sB = sa + A_BYTES;
    #pragma unroll
    for (int t = 0; t < 4; t++) {            // A: 128 rows x 8 segs = 1024 chunks
        int i = tid + t * TPB;
        int r = i >> 3, s = i & 7;
        uint32_t dst = sa + r * 128 + ((s ^ (r & 7)) << 4);
        CP16(dst, A + (size_t)(m0 + r) * K + kc + s * 8);
    }
    #pragma unroll
    for (int t = 0; t < 8; t++) {            // B: 256 rows x 8 segs = 2048 chunks
        int i = tid + t * TPB;
        int r = i >> 3, s = i & 7;
        uint32_t dst = sB + r * 128 + ((s ^ (r & 7)) << 4);
        CP16(dst, B + (size_t)(n0 + r) * K + kc + s * 8);
    }
}

// ---------------- fused GEMM + epilogue ----------------
// GELU=true : A=g_Xh [8192,1024], B=g_W1t [4096,1024], out=g_H (fp16), +b1, erf-GELU
// GELU=false: A=g_H  [8192,4096], B=g_W2t [1024,4096], out=out_f (fp32), +b2
template <bool GELU>
__global__ void __launch_bounds__(TPB, 1)
ffn_gemm(const float* __restrict__ bias, float* __restrict__ out_f) {
    extern __shared__ __align__(1024) uint8_t smem_raw[];
    uint32_t sb = smem_u32(smem_raw);
    const int tid = threadIdx.x;
    const int lane = tid & 31, warp = tid >> 5;
    const int wm = warp & 1;        // 0..1 -> 64-row slice
    const int wn = warp >> 1;       // 0..3 -> 64-col slice
    const int m0 = blockIdx.y * BM;
    const int n0 = blockIdx.x * BN;
    constexpr int K = GELU ? EMB : FF;
    constexpr int Npar = GELU ? FF : EMB;
    constexpr int NC = K / BK;

    const __half* A = GELU ? g_Xh : g_H;
    const __half* B = GELU ? g_W1t : g_W2t;

    float* bias_s = reinterpret_cast<float*>(smem_raw + SM_BIAS);
    for (int i = tid; i < BN; i += TPB) bias_s[i] = bias[n0 + i];

    // ldmatrix lane -> row-offset / k-half mapping (validated in R5 kernel)
    const int a_roff = (lane & 7) + ((lane >> 3) & 1) * 8;
    const int a_hi   = (lane >> 4) & 1;
    const int b_noff = (lane & 7) + ((lane >> 4) & 1) * 8;
    const int b_hi   = (lane >> 3) & 1;

    // 64x64 warp tile: 4 m16 x 8 n8 -> 128 accumulators / thread
    float acc[4][8][4];
    #pragma unroll
    for (int mt = 0; mt < 4; mt++)
        #pragma unroll
        for (int nt = 0; nt < 8; nt++)
            #pragma unroll
            for (int e = 0; e < 4; e++) acc[mt][nt][e] = 0.f;

    // per-lane row byte offsets within a stage
    uint32_t a_rowb[4]; int a_rc[4];
    #pragma unroll
    for (int mt = 0; mt < 4; mt++) {
        int r = wm * 64 + mt * 16 + a_roff;
        a_rowb[mt] = r * 128; a_rc[mt] = r & 7;
    }
    uint32_t b_rowb[4]; int b_rc[4];
    #pragma unroll
    for (int p = 0; p < 4; p++) {
        int r = wn * 64 + p * 16 + b_noff;
        b_rowb[p] = r * 128; b_rc[p] = r & 7;
    }

    // prologue: 3 stages in flight
    load_tile(sb, 0, A, B, m0, n0, 0, K, tid);      CP_COMMIT();
    load_tile(sb, 1, A, B, m0, n0, BK, K, tid);     CP_COMMIT();
    load_tile(sb, 2, A, B, m0, n0, 2 * BK, K, tid); CP_COMMIT();

    for (int i = 0; i < NC; i++) {
        CP_WAIT2();           // chunk i's group complete
        __syncthreads();      // stage (i+3)&3 consumers from last iter are done
        uint32_t sa = sb + SM_TILES + (i & 3) * STG_BYTES;
        uint32_t sB = sa + A_BYTES;

        // issue kk=0 fragment loads first so prefetch issue cost is hidden
        uint32_t ar[4][4], br[4][4];
        #pragma unroll
        for (int mt = 0; mt < 4; mt++) {
            uint32_t ad = sa + a_rowb[mt] + ((a_hi ^ a_rc[mt]) << 4);
            LDSM4(ar[mt][0], ar[mt][1], ar[mt][2], ar[mt][3], ad);
        }
        #pragma unroll
        for (int p = 0; p < 4; p++) {
            uint32_t bd = sB + b_rowb[p] + ((b_hi ^ b_rc[p]) << 4);
            LDSM4(br[p][0], br[p][1], br[p][2], br[p][3], bd);
        }

        int pf = i + 3;
        if (pf < NC) load_tile(sb, pf & 3, A, B, m0, n0, pf * BK, K, tid);
        CP_COMMIT();

        #pragma unroll
        for (int kk = 0; kk < 4; kk++) {
            #pragma unroll
            for (int mt = 0; mt < 4; mt++)
                #pragma unroll
                for (int nt = 0; nt < 8; nt++) {
                    int p = nt >> 1, h = (nt & 1) << 1;
                    MMA16816(acc[mt][nt], ar[mt][0], ar[mt][1], ar[mt][2], ar[mt][3],
                             br[p][h], br[p][h + 1]);
                }
            if (kk < 3) {   // next k16 fragments (regs rotate; ptxas overlaps w/ MMAs)
                int s = 2 * (kk + 1);
                #pragma unroll
                for (int mt = 0; mt < 4; mt++) {
                    uint32_t ad = sa + a_rowb[mt] + (((s + a_hi) ^ a_rc[mt]) << 4);
                    LDSM4(ar[mt][0], ar[mt][1], ar[mt][2], ar[mt][3], ad);
                }
                #pragma unroll
                for (int p = 0; p < 4; p++) {
                    uint32_t bd = sB + b_rowb[p] + (((s + b_hi) ^ b_rc[p]) << 4);
                    LDSM4(br[p][0], br[p][1], br[p][2], br[p][3], bd);
                }
            }
        }
    }

    // ---------------- epilogue: fragments -> bias (+GELU) -> global ----------------
    const int mrow = lane >> 2;            // 0..7
    const int ncol = (lane & 3) * 2;       // 0,2,4,6
    #pragma unroll
    for (int mt = 0; mt < 4; mt++) {
        #pragma unroll
        for (int nt = 0; nt < 8; nt++) {
            int col_l = wn * 64 + nt * 8 + ncol;
            float bi0 = bias_s[col_l], bi1 = bias_s[col_l + 1];
            #pragma unroll
            for (int half = 0; half < 2; half++) {   // d0d1 (m+0) / d2d3 (m+8)
                int row = m0 + wm * 64 + mt * 16 + mrow + half * 8;
                float v0 = acc[mt][nt][2 * half]     + bi0;
                float v1 = acc[mt][nt][2 * half + 1] + bi1;
                if (GELU) {
                    v0 = 0.5f * v0 * (1.0f + erff(v0 * 0.70710678118654752f));
                    v1 = 0.5f * v1 * (1.0f + erff(v1 * 0.70710678118654752f));
                }
                size_t off = (size_t)row * Npar + n0 + col_l;
                if (GELU) {
                    __half2 h2 = __floats2half2_rn(v0, v1);
                    *reinterpret_cast<__half2*>(g_H + off) = h2;
                } else {
                    float2 f2; f2.x = v0; f2.y = v1;
                    *reinterpret_cast<float2*>(out_f + off) = f2;
                }
            }
        }
    }
}

// ---------------- preprocessing (3 launches) ----------------
__global__ void absmean_both_k(const float4* __restrict__ W1,
                               const float4* __restrict__ W2) {
    __shared__ float sm[256];
    const int half = blockIdx.x >> 10;               // 0: W1, 1: W2
    const int blk = blockIdx.x & 1023;
    const float4* w = half ? W2 : W1;
    float s = 0.f;
    const int total = WN / 4;
    for (int i = blk * 256 + threadIdx.x; i < total; i += 1024 * 256) {
        float4 v = w[i];
        s += fabsf(v.x) + fabsf(v.y) + fabsf(v.z) + fabsf(v.w);
    }
    sm[threadIdx.x] = s;
    __syncthreads();
    #pragma unroll
    for (int d = 128; d > 0; d >>= 1) {
        if (threadIdx.x < d) sm[threadIdx.x] += sm[threadIdx.x + d];
        __syncthreads();
    }
    if (threadIdx.x == 0) g_partial[half * 1024 + blk] = sm[0];
}

__global__ void absmean_final_k() {
    __shared__ float sm[1024];
    sm[threadIdx.x] = g_partial[blockIdx.x * 1024 + threadIdx.x];
    __syncthreads();
    #pragma unroll
    for (int d = 512; d > 0; d >>= 1) {
        if (threadIdx.x < d) sm[threadIdx.x] += sm[threadIdx.x + d];
        __syncthreads();
    }
    if (threadIdx.x == 0) g_scale[blockIdx.x] = fmaxf(sm[0] / (float)WN, 1e-8f);
}

// one launch: quantize W1, W2 (ternary fp16) and convert x -> fp16
__global__ void prep_convert_k(const float4* __restrict__ W1,
                               const float4* __restrict__ W2,
                               const float4* __restrict__ x) {
    int i = blockIdx.x * 256 + threadIdx.x;
    const int Q = WN / 4;                    // 1M float4 per weight matrix
    uint2 u;
    if (i < 2 * Q) {
        int which = i >= Q;
        int j = i - which * Q;
        float inv = 1.0f / g_scale[which];
        float4 v = (which ? W2 : W1)[j];
        float a = fminf(fmaxf(rintf(v.x * inv), -1.f), 1.f);
        float b = fminf(fmaxf(rintf(v.y * inv), -1.f), 1.f);
        float c = fminf(fmaxf(rintf(v.z * inv), -1.f), 1.f);
        float d = fminf(fmaxf(rintf(v.w * inv), -1.f), 1.f);
        __half2 h0 = __floats2half2_rn(a, b);
        __half2 h1 = __floats2half2_rn(c, d);
        u.x = *reinterpret_cast<uint32_t*>(&h0);
        u.y = *reinterpret_cast<uint32_t*>(&h1);
        *reinterpret_cast<uint2*>((which ? g_W2t : g_W1t) + (size_t)j * 4) = u;
    } else {
        int j = i - 2 * Q;                  // 0 .. XN/4-1
        float4 v = x[j];
        __half2 h0 = __floats2half2_rn(v.x, v.y);
        __half2 h1 = __floats2half2_rn(v.z, v.w);
        u.x = *reinterpret_cast<uint32_t*>(&h0);
        u.y = *reinterpret_cast<uint32_t*>(&h1);
        *reinterpret_cast<uint2*>(g_Xh + (size_t)j * 4) = u;
    }
}

// ---------------- launcher ----------------
extern "C" void kernel_launch(void* const* d_in, const int* in_sizes, int n_in,
                              void* d_out, int out_size) {
    const float* x  = (const float*)d_in[0];
    const float* W1 = (const float*)d_in[1];
    const float* b1 = (const float*)d_in[2];
    const float* W2 = (const float*)d_in[3];
    const float* b2 = (const float*)d_in[4];
    float* out = (float*)d_out;

    cudaFuncSetAttribute(ffn_gemm<true>,  cudaFuncAttributeMaxDynamicSharedMemorySize, SMEM_TOTAL);
    cudaFuncSetAttribute(ffn_gemm<false>, cudaFuncAttributeMaxDynamicSharedMemorySize, SMEM_TOTAL);

    absmean_both_k<<<2048, 256>>>((const float4*)W1, (const float4*)W2);
    absmean_final_k<<<2, 1024>>>();
    prep_convert_k<<<(2 * (WN / 4) + XN / 4) / 256, 256>>>(
        (const float4*)W1, (const float4*)W2, (const float4*)x);

    ffn_gemm<true><<<dim3(FF / BN, NTOK / BM), TPB, SMEM_TOTAL>>>(b1, nullptr);
    ffn_gemm<false><<<dim3(EMB / BN, NTOK / BM), TPB, SMEM_TOTAL>>>(b2, out);
}